// round 8
// baseline (speedup 1.0000x reference)
#include <cuda_runtime.h>

// ---------------------------------------------------------------------------
// RecNet: xh = x@Wx^T + bx (once); 128x  h = relu(xh + h@Wh^T + bh);
// out = h@Wy^T + by.
//
// Multi-launch (no software grid barrier; kernel boundaries order memory).
// Same verified smem tiling/staging as the plain version; inner loop upgraded
// to packed fp32x2 FMA (SASS FFMA2) with operand pairs built by register
// packing (mov.b64) from plain float4 smem loads. Exact fp32 numerics.
// ---------------------------------------------------------------------------

#define NTHR 128

#define B_  512   // batch
#define H_  512   // hidden
#define DI_ 128   // input dim (= timestep count T)
#define DO_ 256   // output dim
#define TSTEPS 128

typedef unsigned long long ull;

// ---- device scratch (static: no allocations allowed) ----------------------
__device__ float g_WhT[H_ * H_];     // [k][j]  WhT[k*H_+j]  = Wh[j][k]
__device__ float g_WxT[DI_ * H_];    // [k][j]
__device__ float g_xT [DI_ * B_];    // [k][b]
__device__ float g_WyT[H_ * DO_];    // [k][j]
__device__ float g_xh [H_ * B_];     // xh^T : [j][b]
__device__ float g_hbuf[2][H_ * B_]; // h^T  : [j][b]  (ping-pong)

// packed fp32x2 fma (sm_100+); d = a*b + c elementwise on 2 lanes
#define FFMA2(d, a, b, c) \
    asm("fma.rn.f32x2 %0, %1, %2, %3;" : "=l"(d) : "l"(a), "l"(b), "l"(c))
#define PACK2(d, lo, hi) \
    asm("mov.b64 %0, {%1, %2};" : "=l"(d) : "f"(lo), "f"(hi))
#define UNPACK2(lo, hi, s) \
    asm("mov.b64 {%0, %1}, %2;" : "=f"(lo), "=f"(hi) : "l"(s))

// ---- 32x32 tile transpose: src[R][C] row-major -> dst[C][R] ----------------
__device__ __forceinline__ void transpose_job(const float* __restrict__ src,
                                              float* __restrict__ dst,
                                              int R, int C, float* s)
{
    const int TR = R >> 5, TC = C >> 5;
    const int nt = TR * TC;
    const int tid = threadIdx.x;
    const int lr = tid >> 5, lc = tid & 31;
    for (int t = blockIdx.x; t < nt; t += (int)gridDim.x) {
        const int tr = t / TC, tc = t % TC;
        __syncthreads();
#pragma unroll
        for (int i = 0; i < 8; i++) {
            int r = lr + 4 * i;
            s[r * 33 + lc] = src[(tr * 32 + r) * C + tc * 32 + lc];
        }
        __syncthreads();
#pragma unroll
        for (int i = 0; i < 8; i++) {
            int r = lr + 4 * i;
            dst[(tc * 32 + r) * R + tr * 32 + lc] = s[lc * 33 + r];
        }
    }
}

__global__ void __launch_bounds__(NTHR, 1) transpose_kernel(
    const float* __restrict__ x,  const float* __restrict__ Wx,
    const float* __restrict__ Wh, const float* __restrict__ Wy)
{
    __shared__ float s[32 * 33];
    transpose_job(Wh, g_WhT, H_,  H_,  s);   // [512,512] -> [k][j]
    transpose_job(Wx, g_WxT, H_,  DI_, s);   // [512,128] -> [128][512]
    transpose_job(x,  g_xT,  B_,  DI_, s);   // [512,128] -> [128][512]
    transpose_job(Wy, g_WyT, DO_, H_,  s);   // [256,512] -> [512][256]
}

// ---- 64x32 tile GEMM: c[i][j] = sum_k A[k][m0+4tm+i] * B[k][n0+4tn+j] ------
// A: k-major, row length B_ (=512).  Bm: k-major, row length ldb.
// 128 threads: tm = tid>>3 (0..15), tn = tid&7 (0..7); 4m x 4n per thread.
// acc[j][0] = packed (c[0][j], c[1][j]); acc[j][1] = packed (c[2][j], c[3][j]).
__device__ __forceinline__ void gemm_tile(const float* __restrict__ A,
                                          const float* __restrict__ Bm,
                                          int ldb, int nkt, int m0, int n0,
                                          float c[4][4])
{
    __shared__ float sA[32 * 68];   // 32 k x 64 m (+4 pad)
    __shared__ float sB[32 * 36];   // 32 k x 32 n (+4 pad)

    const int tid = threadIdx.x;
    const int tm = tid >> 3, tn = tid & 7;

    ull acc[4][2];
    {
        ull z;
        PACK2(z, 0.f, 0.f);
#pragma unroll
        for (int j = 0; j < 4; j++) { acc[j][0] = z; acc[j][1] = z; }
    }

    float4 pa[4], pb[2];
    // register prefetch of K-tile 0
#pragma unroll
    for (int i = 0; i < 4; i++) {
        int idx = tid + i * NTHR; int kk = idx >> 4, cc = idx & 15;
        pa[i] = *(const float4*)&A[kk * B_ + m0 + 4 * cc];
    }
#pragma unroll
    for (int i = 0; i < 2; i++) {
        int idx = tid + i * NTHR; int kk = idx >> 3, cc = idx & 7;
        pb[i] = *(const float4*)&Bm[kk * ldb + n0 + 4 * cc];
    }

    for (int kt = 0; kt < nkt; kt++) {
        __syncthreads();   // previous tile fully consumed
#pragma unroll
        for (int i = 0; i < 4; i++) {
            int idx = tid + i * NTHR; int kk = idx >> 4, cc = idx & 15;
            *(float4*)&sA[kk * 68 + 4 * cc] = pa[i];
        }
#pragma unroll
        for (int i = 0; i < 2; i++) {
            int idx = tid + i * NTHR; int kk = idx >> 3, cc = idx & 7;
            *(float4*)&sB[kk * 36 + 4 * cc] = pb[i];
        }
        __syncthreads();
        if (kt + 1 < nkt) {  // prefetch next tile under compute
            const float* An = A  + (kt + 1) * 32 * B_;
            const float* Bn = Bm + (kt + 1) * 32 * ldb;
#pragma unroll
            for (int i = 0; i < 4; i++) {
                int idx = tid + i * NTHR; int kk = idx >> 4, cc = idx & 15;
                pa[i] = *(const float4*)&An[kk * B_ + m0 + 4 * cc];
            }
#pragma unroll
            for (int i = 0; i < 2; i++) {
                int idx = tid + i * NTHR; int kk = idx >> 3, cc = idx & 7;
                pb[i] = *(const float4*)&Bn[kk * ldb + n0 + 4 * cc];
            }
        }
#pragma unroll 8
        for (int k = 0; k < 32; k++) {
            float4 av = *(const float4*)&sA[k * 68 + 4 * tm];
            float4 bv = *(const float4*)&sB[k * 36 + 4 * tn];
            ull a01, a23;
            PACK2(a01, av.x, av.y);     // m rows 4tm+0, 4tm+1
            PACK2(a23, av.z, av.w);     // m rows 4tm+2, 4tm+3
            float bn[4] = {bv.x, bv.y, bv.z, bv.w};
#pragma unroll
            for (int j = 0; j < 4; j++) {
                ull bb;
                PACK2(bb, bn[j], bn[j]);
                FFMA2(acc[j][0], a01, bb, acc[j][0]);
                FFMA2(acc[j][1], a23, bb, acc[j][1]);
            }
        }
    }

#pragma unroll
    for (int j = 0; j < 4; j++) {
        UNPACK2(c[0][j], c[1][j], acc[j][0]);
        UNPACK2(c[2][j], c[3][j], acc[j][1]);
    }
}

// ---- phase A: xh^T = (x @ Wx^T + bx)^T ; h1 = relu(xh + bh) ----------------
__global__ void __launch_bounds__(NTHR, 1) phaseA_kernel(
    const float* __restrict__ bx, const float* __restrict__ bh)
{
    float c[4][4];
    const int cta = blockIdx.x;
    const int m0 = (cta & 7) * 64, n0 = (cta >> 3) * 32;
    gemm_tile(g_xT, g_WxT, H_, DI_ / 32, m0, n0, c);

    const int tid = threadIdx.x;
    const int gm = m0 + 4 * (tid >> 3);
    const int tn = tid & 7;
#pragma unroll
    for (int j = 0; j < 4; j++) {
        int n = n0 + 4 * tn + j;
        float bxv = bx[n], bhv = bh[n];
        float4 v, h;
        v.x = c[0][j] + bxv; v.y = c[1][j] + bxv;
        v.z = c[2][j] + bxv; v.w = c[3][j] + bxv;
        *(float4*)&g_xh[n * B_ + gm] = v;
        h.x = fmaxf(v.x + bhv, 0.f); h.y = fmaxf(v.y + bhv, 0.f);
        h.z = fmaxf(v.z + bhv, 0.f); h.w = fmaxf(v.w + bhv, 0.f);
        *(float4*)&g_hbuf[0][n * B_ + gm] = h;
    }
}

// ---- one recurrent step: hbuf[cur^1] = relu(xh + hbuf[cur]@Wh^T + bh) ------
__global__ void __launch_bounds__(NTHR, 1) step_kernel(
    int cur, const float* __restrict__ bh)
{
    float c[4][4];
    const int cta = blockIdx.x;
    const int m0 = (cta & 7) * 64, n0 = (cta >> 3) * 32;
    gemm_tile(g_hbuf[cur], g_WhT, H_, H_ / 32, m0, n0, c);

    const int tid = threadIdx.x;
    const int gm = m0 + 4 * (tid >> 3);
    const int tn = tid & 7;
    float* __restrict__ dst = g_hbuf[cur ^ 1];
#pragma unroll
    for (int j = 0; j < 4; j++) {
        int n = n0 + 4 * tn + j;
        float bhv = bh[n];
        float4 xv = *(const float4*)&g_xh[n * B_ + gm];
        float4 h;
        h.x = fmaxf(c[0][j] + xv.x + bhv, 0.f);
        h.y = fmaxf(c[1][j] + xv.y + bhv, 0.f);
        h.z = fmaxf(c[2][j] + xv.z + bhv, 0.f);
        h.w = fmaxf(c[3][j] + xv.w + bhv, 0.f);
        *(float4*)&dst[n * B_ + gm] = h;
    }
}

// ---- output: out = h_final @ Wy^T + by  (h_final in g_hbuf[1]) -------------
__global__ void __launch_bounds__(NTHR, 1) out_kernel(
    const float* __restrict__ by, float* __restrict__ out)
{
    float c[4][4];
    const int cta = blockIdx.x;                 // 64 CTAs: 8 m x 8 n tiles
    const int m0 = (cta & 7) * 64, n0 = (cta >> 3) * 32;
    gemm_tile(g_hbuf[(TSTEPS - 1) & 1], g_WyT, DO_, H_ / 32, m0, n0, c);

    const int tid = threadIdx.x;
    const int gm = m0 + 4 * (tid >> 3);
    const int gn = n0 + 4 * (tid & 7);
    float b0 = by[gn], b1 = by[gn + 1], b2 = by[gn + 2], b3 = by[gn + 3];
#pragma unroll
    for (int i = 0; i < 4; i++) {
        float4 o;
        o.x = c[i][0] + b0; o.y = c[i][1] + b1;
        o.z = c[i][2] + b2; o.w = c[i][3] + b3;
        *(float4*)&out[(gm + i) * DO_ + gn] = o;
    }
}

// ---------------------------------------------------------------------------
extern "C" void kernel_launch(void* const* d_in, const int* in_sizes, int n_in,
                              void* d_out, int out_size)
{
    const float* x  = (const float*)d_in[0];  // [512,128]
    const float* Wx = (const float*)d_in[1];  // [512,128]
    const float* bx = (const float*)d_in[2];  // [512]
    const float* Wh = (const float*)d_in[3];  // [512,512]
    const float* bh = (const float*)d_in[4];  // [512]
    const float* Wy = (const float*)d_in[5];  // [256,512]
    const float* by = (const float*)d_in[6];  // [256]
    float* out = (float*)d_out;               // [512,256]

    transpose_kernel<<<128, NTHR>>>(x, Wx, Wh, Wy);
    phaseA_kernel<<<128, NTHR>>>(bx, bh);              // h1 in g_hbuf[0]
    for (int t = 1; t < TSTEPS; t++)
        step_kernel<<<128, NTHR>>>((t - 1) & 1, bh);   // final h in g_hbuf[1]
    out_kernel<<<64, NTHR>>>(by, out);
}